// round 12
// baseline (speedup 1.0000x reference)
#include <cuda_runtime.h>
#include <cuda_fp16.h>
#include <cstdint>
#include <math.h>

#define D_MODEL   2048
#define NUM_HEADS 16
#define HEAD_DIM  128
#define KV_DIM    512
#define QKV_N     3072
#define BATCHN    2
#define SEQ       2048
#define M_TOT     4096

// ---------------------------------------------------------------------------
// Scratch (__device__ globals; allocation-free rule)
// ---------------------------------------------------------------------------
__device__ float g_qkv[(size_t)M_TOT * QKV_N];
__device__ __align__(16) __half g_Ax[(size_t)M_TOT * D_MODEL];
__device__ __align__(16) __half g_Aatt[(size_t)M_TOT * D_MODEL];
__device__ __align__(16) __half g_Bqkv[(size_t)QKV_N * D_MODEL];
__device__ __align__(16) __half g_Bo[(size_t)D_MODEL * D_MODEL];
__device__ __align__(16) __half g_Qh[(size_t)BATCHN * NUM_HEADS * SEQ * HEAD_DIM];
__device__ __align__(16) __half g_Kh[(size_t)BATCHN * 4 * SEQ * HEAD_DIM];
__device__ __align__(16) __half g_Vt[(size_t)BATCHN * 4 * HEAD_DIM * SEQ];

__device__ __forceinline__ uint32_t smem_u32(const void* p) {
    uint32_t a;
    asm("{ .reg .u64 t; cvta.to.shared.u64 t, %1; cvt.u32.u64 %0, t; }" : "=r"(a) : "l"(p));
    return a;
}
__device__ __forceinline__ void ldsm_x4(uint32_t* r, uint32_t addr) {
    asm volatile("ldmatrix.sync.aligned.m8n8.x4.shared.b16 {%0,%1,%2,%3}, [%4];"
                 : "=r"(r[0]), "=r"(r[1]), "=r"(r[2]), "=r"(r[3]) : "r"(addr) : "memory");
}
__device__ __forceinline__ void mma16816(float* c, const uint32_t* a,
                                         uint32_t b0, uint32_t b1) {
    asm volatile("mma.sync.aligned.m16n8k16.row.col.f32.f16.f16.f32 "
                 "{%0,%1,%2,%3},{%4,%5,%6,%7},{%8,%9},{%0,%1,%2,%3};"
                 : "+f"(c[0]), "+f"(c[1]), "+f"(c[2]), "+f"(c[3])
                 : "r"(a[0]), "r"(a[1]), "r"(a[2]), "r"(a[3]), "r"(b0), "r"(b1));
}
__device__ __forceinline__ uint32_t packh2(float a, float b) {
    __half2 h = __floats2half2_rn(a, b);
    return *(uint32_t*)&h;
}
#define CP_ASYNC16(dst, src) \
    asm volatile("cp.async.cg.shared.global [%0], [%1], 16;\n" :: "r"(dst), "l"(src))
#define CP_COMMIT() asm volatile("cp.async.commit_group;\n" ::: "memory")
#define CP_WAIT0()  asm volatile("cp.async.wait_group 0;\n" ::: "memory")
#define CP_WAIT1()  asm volatile("cp.async.wait_group 1;\n" ::: "memory")

// 3-stage pipeline buffers: A = 3 x (256 rows x 40 halves), B = 3 x (128 x 40)
#define GSM_HALVES (3 * 10240 + 3 * 5120)
#define GSM_BYTES  (GSM_HALVES * 2)          // 92160 B

// ---------------------------------------------------------------------------
// fp16 tensor-core GEMM, 256x128 CTA tile, 3-stage cp.async pipeline.
// C[M,N] = A[M,K] @ B[N,K]^T, fp32 out. 8 warps, warp tile 64x64.
// ---------------------------------------------------------------------------
__global__ void __launch_bounds__(256, 1) gemm_mma(const __half* __restrict__ A,
                                                   const __half* __restrict__ B,
                                                   float* __restrict__ C,
                                                   int N, int K)
{
    extern __shared__ __half gsm[];
    const int tid = threadIdx.x;
    const int w = tid >> 5, l = tid & 31;
    const int brow = blockIdx.y * 256, bcol = blockIdx.x * 128;
    const int wm = (w >> 1) * 64, wn = (w & 1) * 64;
    const uint32_t sa0 = smem_u32(gsm);                  // A stages: p * 10240 halves
    const uint32_t sb0 = smem_u32(gsm + 3 * 10240);      // B stages: p * 5120 halves
    const int NIT = K >> 5;

    float acc[4][8][4];
#pragma unroll
    for (int a = 0; a < 4; a++)
#pragma unroll
        for (int b2 = 0; b2 < 8; b2++)
#pragma unroll
            for (int c = 0; c < 4; c++) acc[a][b2][c] = 0.f;

    const int lr0 = tid >> 2, lkc = tid & 3;
    const __half* Ag = A + (size_t)brow * K;
    const __half* Bg = B + (size_t)bcol * K;

    auto LOAD = [&](int buf, int k0) {
#pragma unroll
        for (int j = 0; j < 4; j++) {        // A: 256 rows
            int r = lr0 + j * 64;
            uint32_t so = (uint32_t)(buf * 10240 + r * 40 + lkc * 8) * 2;
            CP_ASYNC16(sa0 + so, Ag + (size_t)r * K + k0 + lkc * 8);
        }
#pragma unroll
        for (int j = 0; j < 2; j++) {        // B: 128 rows
            int r = lr0 + j * 64;
            uint32_t so = (uint32_t)(buf * 5120 + r * 40 + lkc * 8) * 2;
            CP_ASYNC16(sb0 + so, Bg + (size_t)r * K + k0 + lkc * 8);
        }
        CP_COMMIT();
    };

    LOAD(0, 0);
    LOAD(1, 32);

    for (int i = 0; i < NIT; i++) {
        const int p = i % 3;
        if (i == NIT - 1) { CP_WAIT0(); } else { CP_WAIT1(); }
        __syncthreads();
        if (i + 2 < NIT) LOAD((i + 2) % 3, (i + 2) * 32);

        // B fragments: 8 n-frags, each ldsm.x4 covers k0..31
        uint32_t bfr[8][4];
#pragma unroll
        for (int nf = 0; nf < 8; nf++)
            ldsm_x4(bfr[nf], sb0 + (uint32_t)(p * 5120 +
                    (wn + nf * 8 + (l & 7)) * 40 + (l >> 3) * 8) * 2);

#pragma unroll
        for (int s = 0; s < 2; s++) {
            uint32_t afr[4][4];
#pragma unroll
            for (int mf = 0; mf < 4; mf++) {
                int row = wm + mf * 16 + ((l >> 3) & 1) * 8 + (l & 7);
                int chunk = 2 * s + (l >> 4);
                ldsm_x4(afr[mf], sa0 + (uint32_t)(p * 10240 + row * 40 + chunk * 8) * 2);
            }
#pragma unroll
            for (int mf = 0; mf < 4; mf++)
#pragma unroll
                for (int nf = 0; nf < 8; nf++)
                    mma16816(acc[mf][nf], afr[mf], bfr[nf][2 * s], bfr[nf][2 * s + 1]);
        }
    }

#pragma unroll
    for (int mf = 0; mf < 4; mf++) {
        int r0 = brow + wm + mf * 16 + (l >> 2);
#pragma unroll
        for (int nf = 0; nf < 8; nf++) {
            int c = bcol + wn + nf * 8 + (l & 3) * 2;
            *(float2*)(C + (size_t)r0 * N + c) = make_float2(acc[mf][nf][0], acc[mf][nf][1]);
            *(float2*)(C + (size_t)(r0 + 8) * N + c) = make_float2(acc[mf][nf][2], acc[mf][nf][3]);
        }
    }
}

// ---------------------------------------------------------------------------
// Converts (verified)
// ---------------------------------------------------------------------------
__global__ void conv_half4(const float* __restrict__ s, __half* __restrict__ d)
{
    int i = blockIdx.x * blockDim.x + threadIdx.x;
    float4 v = ((const float4*)s)[i];
    ((__half2*)d)[2 * i]     = __floats2half2_rn(v.x, v.y);
    ((__half2*)d)[2 * i + 1] = __floats2half2_rn(v.z, v.w);
}

__global__ void convT_half(const float* __restrict__ W,
                           __half* __restrict__ dst, int Ncols)
{
    __shared__ float t[32][33];
    int k0 = blockIdx.y * 32, n0 = blockIdx.x * 32;
    int tx = threadIdx.x, ty = threadIdx.y;
#pragma unroll
    for (int r = 0; r < 32; r += 8)
        t[ty + r][tx] = W[(size_t)(k0 + ty + r) * Ncols + n0 + tx];
    __syncthreads();
#pragma unroll
    for (int r = 0; r < 32; r += 8)
        dst[(size_t)(n0 + ty + r) * D_MODEL + k0 + tx] = __float2half(t[tx][ty + r]);
}

__global__ void rope_conv(const float* __restrict__ sinp,
                          const float* __restrict__ cosp)
{
    int i = blockIdx.x * blockDim.x + threadIdx.x;
    int d  = i & 63;
    int hh = (i >> 6) % 20;
    int m  = i / (64 * 20);
    int t  = m & (SEQ - 1);
    int b  = m >> 11;
    int col = (hh < 16) ? hh * 128 : D_MODEL + (hh - 16) * 128;
    float s = sinp[t * 64 + d];
    float c = cosp[t * 64 + d];
    const float* p = g_qkv + (size_t)m * QKV_N + col;
    float x1 = p[d], x2 = p[d + 64];
    float y1 = x1 * c - x2 * s;
    float y2 = x2 * c + x1 * s;
    __half* dst = (hh < 16)
        ? g_Qh + (((size_t)(b * 16 + hh)) * SEQ + t) * HEAD_DIM
        : g_Kh + (((size_t)(b * 4 + (hh - 16))) * SEQ + t) * HEAD_DIM;
    dst[d]      = __float2half(y1);
    dst[d + 64] = __float2half(y2);
}

__global__ void vt_conv()
{
    __shared__ float t[32][33];
    int n0 = blockIdx.x * 32;
    int k0 = blockIdx.y * 32;
    int z  = blockIdx.z;
    int b = z >> 2, g = z & 3;
    int tx = threadIdx.x, ty = threadIdx.y;
#pragma unroll
    for (int r = 0; r < 32; r += 8)
        t[ty + r][tx] = g_qkv[(size_t)(b * SEQ + k0 + ty + r) * QKV_N +
                              D_MODEL + KV_DIM + g * 128 + n0 + tx];
    __syncthreads();
#pragma unroll
    for (int r = 0; r < 32; r += 8)
        g_Vt[((size_t)z * HEAD_DIM + n0 + ty + r) * SEQ + k0 + tx] =
            __float2half(t[tx][ty + r]);
}

// ---------------------------------------------------------------------------
// FA-2-style tensor-core attention (TQ=128) — byte-identical to R11 passing.
// ---------------------------------------------------------------------------
#define BS_Q   0
#define BS_K   34816
#define BS_V   69632
#define BS_KD  106496
#define ATT_SMEM 107008

__global__ void __launch_bounds__(256, 1) attn_mma(const int* __restrict__ doc_ids)
{
    extern __shared__ char smem[];
    const uint32_t sb = smem_u32(smem);
    const uint32_t uQ = sb + BS_Q;

    const int qt = (int)(gridDim.x - 1) - (int)blockIdx.x;
    const int h = blockIdx.y, b = blockIdx.z;
    const int g = h >> 2;
    const int tid = threadIdx.x, w = tid >> 5, l = tid & 31;
    const int wm = w * 16;
    const int t0 = qt * 128;
    const float scale = 0.08838834764831845f;

    const __half* qsrc = g_Qh + (((size_t)(b * 16 + h)) * SEQ + t0) * HEAD_DIM;
#pragma unroll
    for (int j = 0; j < 8; j++) {
        int idx = tid + j * 256;
        int r = idx >> 4, c = idx & 15;
        CP_ASYNC16(uQ + (uint32_t)(r * 136 + c * 8) * 2, qsrc + r * 128 + c * 8);
    }
    CP_COMMIT();

    const int r0 = wm + (l >> 2);
    const int qi0 = t0 + r0, qi8 = qi0 + 8;
    const int dbase = b * SEQ;
    const int qd0 = doc_ids[dbase + qi0];
    const int qd8 = doc_ids[dbase + qi8];
    const int dq_min = doc_ids[dbase + t0];

    float rowm0 = -1e30f, rowm8 = -1e30f, rowl0 = 0.f, rowl8 = 0.f;
    float acc[16][4];
#pragma unroll
    for (int nf = 0; nf < 16; nf++)
#pragma unroll
        for (int q = 0; q < 4; q++) acc[nf][q] = 0.f;

    const __half* kbase = g_Kh + ((size_t)(b * 4 + g)) * SEQ * HEAD_DIM;
    const __half* vbase = g_Vt + ((size_t)(b * 4 + g) * HEAD_DIM) * SEQ;

    auto load_tile = [&](int t, int buf) {
        const __half* ks = kbase + (size_t)t * 64 * HEAD_DIM;
        const __half* vs = vbase + t * 64;
        uint32_t uk = sb + BS_K + buf * 17408;
        uint32_t uv = sb + BS_V + buf * 18432;
#pragma unroll
        for (int j = 0; j < 4; j++) {
            int idx = tid + j * 256;
            int r = idx >> 4, c = idx & 15;
            CP_ASYNC16(uk + (uint32_t)(r * 136 + c * 8) * 2, ks + r * 128 + c * 8);
        }
#pragma unroll
        for (int j = 0; j < 4; j++) {
            int idx = tid + j * 256;
            int r = idx >> 3, c = idx & 7;
            CP_ASYNC16(uv + (uint32_t)(r * 72 + c * 8) * 2, vs + (size_t)r * SEQ + c * 8);
        }
        if (tid < 64)
            ((int*)(smem + BS_KD + buf * 256))[tid] = doc_ids[dbase + t * 64 + tid];
    };

    const int ktmax = 2 * qt + 1;
    int kt = 0;
    while (kt <= ktmax && doc_ids[dbase + kt * 64 + 63] < dq_min) kt++;

    int p = 0;
    load_tile(kt, 0);
    CP_COMMIT();
    CP_WAIT0();
    __syncthreads();

    uint32_t qfr[4][2][4];
#pragma unroll
    for (int kb = 0; kb < 4; kb++)
#pragma unroll
        for (int s = 0; s < 2; s++)
            ldsm_x4(qfr[kb][s], uQ + (uint32_t)((wm + ((l >> 3) & 1) * 8 + (l & 7)) * 136 +
                    (kb * 4 + 2 * s + (l >> 4)) * 8) * 2);

    while (true) {
        int ktn = kt + 1;
        while (ktn <= ktmax && doc_ids[dbase + ktn * 64 + 63] < dq_min) ktn++;
        const bool havenext = (ktn <= ktmax);
        if (havenext) { load_tile(ktn, p ^ 1); CP_COMMIT(); }

        const uint32_t uk = sb + BS_K + p * 17408;
        const uint32_t uv = sb + BS_V + p * 18432;
        const int* kd = (const int*)(smem + BS_KD + p * 256);

        float e[8][4];
#pragma unroll
        for (int nf = 0; nf < 8; nf++)
#pragma unroll
            for (int q = 0; q < 4; q++) e[nf][q] = 0.f;

#pragma unroll
        for (int kb = 0; kb < 4; kb++) {
#pragma unroll
            for (int nf = 0; nf < 8; nf++) {
                uint32_t bfr[4];
                ldsm_x4(bfr, uk + (uint32_t)((nf * 8 + (l & 7)) * 136 +
                        (kb * 4 + (l >> 3)) * 8) * 2);
                mma16816(e[nf], qfr[kb][0], bfr[0], bfr[1]);
                mma16816(e[nf], qfr[kb][1], bfr[2], bfr[3]);
            }
        }

        const int kcol0 = kt * 64;
#pragma unroll
        for (int nf = 0; nf < 8; nf++) {
            int c = nf * 8 + (l & 3) * 2;
            int kj = kcol0 + c;
            int kdc = kd[c], kdc1 = kd[c + 1];
            e[nf][0] = (kj     > qi0 || qd0 != kdc ) ? -1e30f : e[nf][0] * scale;
            e[nf][1] = (kj + 1 > qi0 || qd0 != kdc1) ? -1e30f : e[nf][1] * scale;
            e[nf][2] = (kj     > qi8 || qd8 != kdc ) ? -1e30f : e[nf][2] * scale;
            e[nf][3] = (kj + 1 > qi8 || qd8 != kdc1) ? -1e30f : e[nf][3] * scale;
        }

        float mx0 = rowm0, mx8 = rowm8;
#pragma unroll
        for (int nf = 0; nf < 8; nf++) {
            mx0 = fmaxf(mx0, fmaxf(e[nf][0], e[nf][1]));
            mx8 = fmaxf(mx8, fmaxf(e[nf][2], e[nf][3]));
        }
        mx0 = fmaxf(mx0, __shfl_xor_sync(0xffffffffu, mx0, 1));
        mx0 = fmaxf(mx0, __shfl_xor_sync(0xffffffffu, mx0, 2));
        mx8 = fmaxf(mx8, __shfl_xor_sync(0xffffffffu, mx8, 1));
        mx8 = fmaxf(mx8, __shfl_xor_sync(0xffffffffu, mx8, 2));

        float cf0 = __expf(rowm0 - mx0);
        float cf8 = __expf(rowm8 - mx8);
        float ts0 = 0.f, ts8 = 0.f;
#pragma unroll
        for (int nf = 0; nf < 8; nf++) {
            e[nf][0] = (e[nf][0] > -1e29f) ? __expf(e[nf][0] - mx0) : 0.f;
            e[nf][1] = (e[nf][1] > -1e29f) ? __expf(e[nf][1] - mx0) : 0.f;
            e[nf][2] = (e[nf][2] > -1e29f) ? __expf(e[nf][2] - mx8) : 0.f;
            e[nf][3] = (e[nf][3] > -1e29f) ? __expf(e[nf][3] - mx8) : 0.f;
            ts0 += e[nf][0] + e[nf][1];
            ts8 += e[nf][2] + e[nf][3];
        }
        ts0 += __shfl_xor_sync(0xffffffffu, ts0, 1);
        ts0 += __shfl_xor_sync(0xffffffffu, ts0, 2);
        ts8 += __shfl_xor_sync(0xffffffffu, ts8, 1);
        ts8 += __shfl_xor_sync(0xffffffffu, ts8, 2);
        rowm0 = mx0; rowm8 = mx8;
        rowl0 = rowl0 * cf0 + ts0;
        rowl8 = rowl8 * cf8 + ts8;

#pragma unroll
        for (int nf = 0; nf < 16; nf++) {
            acc[nf][0] *= cf0; acc[nf][1] *= cf0;
            acc[nf][2] *= cf8; acc[nf][3] *= cf8;
        }

        uint32_t pa[4][4];
#pragma unroll
        for (int j = 0; j < 4; j++) {
            pa[j][0] = packh2(e[2 * j][0],     e[2 * j][1]);
            pa[j][1] = packh2(e[2 * j][2],     e[2 * j][3]);
            pa[j][2] = packh2(e[2 * j + 1][0], e[2 * j + 1][1]);
            pa[j][3] = packh2(e[2 * j + 1][2], e[2 * j + 1][3]);
        }
#pragma unroll
        for (int kb2 = 0; kb2 < 2; kb2++) {
#pragma unroll
            for (int nf = 0; nf < 16; nf++) {
                uint32_t bfr[4];
                ldsm_x4(bfr, uv + (uint32_t)((nf * 8 + (l & 7)) * 72 +
                        (kb2 * 4 + (l >> 3)) * 8) * 2);
                mma16816(acc[nf], pa[2 * kb2],     bfr[0], bfr[1]);
                mma16816(acc[nf], pa[2 * kb2 + 1], bfr[2], bfr[3]);
            }
        }

        if (!havenext) break;
        CP_WAIT0();
        __syncthreads();
        p ^= 1;
        kt = ktn;
    }

    {
        float inv0 = 1.f / rowl0, inv8 = 1.f / rowl8;
        size_t row0 = (size_t)(dbase + qi0) * D_MODEL;
        size_t row8 = (size_t)(dbase + qi8) * D_MODEL;
#pragma unroll
        for (int nf = 0; nf < 16; nf++) {
            int c = h * 128 + nf * 8 + (l & 3) * 2;
            *(__half2*)(g_Aatt + row0 + c) =
                __floats2half2_rn(acc[nf][0] * inv0, acc[nf][1] * inv0);
            *(__half2*)(g_Aatt + row8 + c) =
                __floats2half2_rn(acc[nf][2] * inv8, acc[nf][3] * inv8);
        }
    }
}

// ---------------------------------------------------------------------------
extern "C" void kernel_launch(void* const* d_in, const int* in_sizes, int n_in,
                              void* d_out, int out_size)
{
    const float* x    = (const float*)d_in[0];
    const float* sinp = (const float*)d_in[1];
    const float* cosp = (const float*)d_in[2];
    const int*   doc  = (const int*)d_in[3];
    const float* Wqkv = (const float*)d_in[4];
    const float* Wo   = (const float*)d_in[5];
    float* out = (float*)d_out;

    float* qkv_ptr;
    __half *ax, *aatt, *bqkv, *bo;
    cudaGetSymbolAddress((void**)&qkv_ptr, g_qkv);
    cudaGetSymbolAddress((void**)&ax,   g_Ax);
    cudaGetSymbolAddress((void**)&aatt, g_Aatt);
    cudaGetSymbolAddress((void**)&bqkv, g_Bqkv);
    cudaGetSymbolAddress((void**)&bo,   g_Bo);

    cudaFuncSetAttribute(gemm_mma, cudaFuncAttributeMaxDynamicSharedMemorySize,
                         GSM_BYTES);
    cudaFuncSetAttribute(attn_mma, cudaFuncAttributeMaxDynamicSharedMemorySize,
                         ATT_SMEM);

    // 1) fp16 conversions
    conv_half4<<<(M_TOT * D_MODEL / 4) / 256, 256>>>(x, ax);
    convT_half<<<dim3(QKV_N / 32, D_MODEL / 32), dim3(32, 8)>>>(Wqkv, bqkv, QKV_N);

    // 2) QKV projection (256x128 tiles)
    gemm_mma<<<dim3(QKV_N / 128, M_TOT / 256), 256, GSM_BYTES>>>(ax, bqkv, qkv_ptr,
                                                                 QKV_N, D_MODEL);

    // 3) RoPE + head-major fp16 Q/K; V transpose
    rope_conv<<<(M_TOT * 20 * 64) / 256, 256>>>(sinp, cosp);
    vt_conv<<<dim3(HEAD_DIM / 32, SEQ / 32, BATCHN * 4), dim3(32, 8)>>>();

    // 4) FA-2-style tensor-core attention (unchanged from R11)
    attn_mma<<<dim3(SEQ / 128, NUM_HEADS, BATCHN), 256, ATT_SMEM>>>(doc);

    // 5) Output projection (256x128 tiles)
    convT_half<<<dim3(D_MODEL / 32, D_MODEL / 32), dim3(32, 8)>>>(Wo, bo, D_MODEL);
    gemm_mma<<<dim3(D_MODEL / 128, M_TOT / 256), 256, GSM_BYTES>>>(aatt, bo, out,
                                                                   D_MODEL, D_MODEL);
}

// round 15
// speedup vs baseline: 1.0742x; 1.0742x over previous
#include <cuda_runtime.h>
#include <cuda_fp16.h>
#include <cstdint>
#include <math.h>

#define D_MODEL   2048
#define NUM_HEADS 16
#define HEAD_DIM  128
#define KV_DIM    512
#define QKV_N     3072
#define BATCHN    2
#define SEQ       2048
#define M_TOT     4096

// ---------------------------------------------------------------------------
// Scratch (__device__ globals; allocation-free rule)
// ---------------------------------------------------------------------------
__device__ float g_qkv[(size_t)M_TOT * QKV_N];
__device__ __align__(16) __half g_Ax[(size_t)M_TOT * D_MODEL];
__device__ __align__(16) __half g_Aatt[(size_t)M_TOT * D_MODEL];
__device__ __align__(16) __half g_Bqkv[(size_t)QKV_N * D_MODEL];
__device__ __align__(16) __half g_Bo[(size_t)D_MODEL * D_MODEL];
__device__ __align__(16) __half g_Qh[(size_t)BATCHN * NUM_HEADS * SEQ * HEAD_DIM];
__device__ __align__(16) __half g_Kh[(size_t)BATCHN * 4 * SEQ * HEAD_DIM];
__device__ __align__(16) __half g_Vt[(size_t)BATCHN * 4 * HEAD_DIM * SEQ];

__device__ __forceinline__ uint32_t smem_u32(const void* p) {
    uint32_t a;
    asm("{ .reg .u64 t; cvta.to.shared.u64 t, %1; cvt.u32.u64 %0, t; }" : "=r"(a) : "l"(p));
    return a;
}
__device__ __forceinline__ void ldsm_x4(uint32_t* r, uint32_t addr) {
    asm volatile("ldmatrix.sync.aligned.m8n8.x4.shared.b16 {%0,%1,%2,%3}, [%4];"
                 : "=r"(r[0]), "=r"(r[1]), "=r"(r[2]), "=r"(r[3]) : "r"(addr) : "memory");
}
__device__ __forceinline__ void mma16816(float* c, const uint32_t* a,
                                         uint32_t b0, uint32_t b1) {
    asm volatile("mma.sync.aligned.m16n8k16.row.col.f32.f16.f16.f32 "
                 "{%0,%1,%2,%3},{%4,%5,%6,%7},{%8,%9},{%0,%1,%2,%3};"
                 : "+f"(c[0]), "+f"(c[1]), "+f"(c[2]), "+f"(c[3])
                 : "r"(a[0]), "r"(a[1]), "r"(a[2]), "r"(a[3]), "r"(b0), "r"(b1));
}
__device__ __forceinline__ uint32_t packh2(float a, float b) {
    __half2 h = __floats2half2_rn(a, b);
    return *(uint32_t*)&h;
}
__device__ __forceinline__ float ex2f(float x) {
    float y; asm("ex2.approx.f32 %0, %1;" : "=f"(y) : "f"(x)); return y;
}
#define CP_ASYNC16(dst, src) \
    asm volatile("cp.async.cg.shared.global [%0], [%1], 16;\n" :: "r"(dst), "l"(src))
#define CP_COMMIT() asm volatile("cp.async.commit_group;\n" ::: "memory")
#define CP_WAIT0()  asm volatile("cp.async.wait_group 0;\n" ::: "memory")
#define CP_WAIT1()  asm volatile("cp.async.wait_group 1;\n" ::: "memory")

#define GSM_BYTES (6 * 5120 * 2)   // 3-stage pipeline: 3 A-bufs + 3 B-bufs

// ---------------------------------------------------------------------------
// fp16 tensor-core GEMM, 128x128 tile, 3-stage cp.async (exact R11 config).
// ---------------------------------------------------------------------------
__global__ void __launch_bounds__(256, 2) gemm_mma(const __half* __restrict__ A,
                                                   const __half* __restrict__ B,
                                                   float* __restrict__ C,
                                                   int N, int K)
{
    extern __shared__ __half gsm[];
    __half* As = gsm;                 // [3][5120]
    __half* Bs = gsm + 3 * 5120;      // [3][5120]
    const int tid = threadIdx.x;
    const int w = tid >> 5, l = tid & 31;
    const int brow = blockIdx.y * 128, bcol = blockIdx.x * 128;
    const int wm = (w >> 2) * 64, wn = (w & 3) * 32;
    const uint32_t sa0 = smem_u32(As), sb0 = smem_u32(Bs);
    const int NIT = K >> 5;

    float acc[4][4][4];
#pragma unroll
    for (int a = 0; a < 4; a++)
#pragma unroll
        for (int b2 = 0; b2 < 4; b2++)
#pragma unroll
            for (int c = 0; c < 4; c++) acc[a][b2][c] = 0.f;

    const int lr0 = tid >> 2, lkc = tid & 3;
    const __half* Ag = A + (size_t)brow * K;
    const __half* Bg = B + (size_t)bcol * K;

    auto LOAD = [&](int buf, int k0) {
#pragma unroll
        for (int j = 0; j < 2; j++) {
            int r = lr0 + j * 64;
            uint32_t so = (uint32_t)(buf * 5120 + r * 40 + lkc * 8) * 2;
            CP_ASYNC16(sa0 + so, Ag + (size_t)r * K + k0 + lkc * 8);
            CP_ASYNC16(sb0 + so, Bg + (size_t)r * K + k0 + lkc * 8);
        }
        CP_COMMIT();
    };

    LOAD(0, 0);
    LOAD(1, 32);

    for (int i = 0; i < NIT; i++) {
        const int p = i % 3;
        if (i == NIT - 1) { CP_WAIT0(); } else { CP_WAIT1(); }
        __syncthreads();
        if (i + 2 < NIT) LOAD((i + 2) % 3, (i + 2) * 32);

        uint32_t bfr[4][4];
#pragma unroll
        for (int nf = 0; nf < 4; nf++)
            ldsm_x4(bfr[nf], sb0 + (uint32_t)(p * 5120 +
                    (wn + nf * 8 + (l & 7)) * 40 + (l >> 3) * 8) * 2);

#pragma unroll
        for (int s = 0; s < 2; s++) {
            uint32_t afr[4][4];
#pragma unroll
            for (int mf = 0; mf < 4; mf++) {
                int row = wm + mf * 16 + ((l >> 3) & 1) * 8 + (l & 7);
                int chunk = 2 * s + (l >> 4);
                ldsm_x4(afr[mf], sa0 + (uint32_t)(p * 5120 + row * 40 + chunk * 8) * 2);
            }
#pragma unroll
            for (int mf = 0; mf < 4; mf++)
#pragma unroll
                for (int nf = 0; nf < 4; nf++)
                    mma16816(acc[mf][nf], afr[mf], bfr[nf][2 * s], bfr[nf][2 * s + 1]);
        }
    }

#pragma unroll
    for (int mf = 0; mf < 4; mf++) {
        int r0 = brow + wm + mf * 16 + (l >> 2);
#pragma unroll
        for (int nf = 0; nf < 4; nf++) {
            int c = bcol + wn + nf * 8 + (l & 3) * 2;
            *(float2*)(C + (size_t)r0 * N + c) = make_float2(acc[mf][nf][0], acc[mf][nf][1]);
            *(float2*)(C + (size_t)(r0 + 8) * N + c) = make_float2(acc[mf][nf][2], acc[mf][nf][3]);
        }
    }
}

// ---------------------------------------------------------------------------
// Converts (verified)
// ---------------------------------------------------------------------------
__global__ void conv_half4(const float* __restrict__ s, __half* __restrict__ d)
{
    int i = blockIdx.x * blockDim.x + threadIdx.x;
    float4 v = ((const float4*)s)[i];
    ((__half2*)d)[2 * i]     = __floats2half2_rn(v.x, v.y);
    ((__half2*)d)[2 * i + 1] = __floats2half2_rn(v.z, v.w);
}

__global__ void convT_half(const float* __restrict__ W,
                           __half* __restrict__ dst, int Ncols)
{
    __shared__ float t[32][33];
    int k0 = blockIdx.y * 32, n0 = blockIdx.x * 32;
    int tx = threadIdx.x, ty = threadIdx.y;
#pragma unroll
    for (int r = 0; r < 32; r += 8)
        t[ty + r][tx] = W[(size_t)(k0 + ty + r) * Ncols + n0 + tx];
    __syncthreads();
#pragma unroll
    for (int r = 0; r < 32; r += 8)
        dst[(size_t)(n0 + ty + r) * D_MODEL + k0 + tx] = __float2half(t[tx][ty + r]);
}

__global__ void rope_conv(const float* __restrict__ sinp,
                          const float* __restrict__ cosp)
{
    int i = blockIdx.x * blockDim.x + threadIdx.x;
    int d  = i & 63;
    int hh = (i >> 6) % 20;
    int m  = i / (64 * 20);
    int t  = m & (SEQ - 1);
    int b  = m >> 11;
    int col = (hh < 16) ? hh * 128 : D_MODEL + (hh - 16) * 128;
    float s = sinp[t * 64 + d];
    float c = cosp[t * 64 + d];
    const float* p = g_qkv + (size_t)m * QKV_N + col;
    float x1 = p[d], x2 = p[d + 64];
    float y1 = x1 * c - x2 * s;
    float y2 = x2 * c + x1 * s;
    __half* dst = (hh < 16)
        ? g_Qh + (((size_t)(b * 16 + hh)) * SEQ + t) * HEAD_DIM
        : g_Kh + (((size_t)(b * 4 + (hh - 16))) * SEQ + t) * HEAD_DIM;
    dst[d]      = __float2half(y1);
    dst[d + 64] = __float2half(y2);
}

__global__ void vt_conv()
{
    __shared__ float t[32][33];
    int n0 = blockIdx.x * 32;
    int k0 = blockIdx.y * 32;
    int z  = blockIdx.z;
    int b = z >> 2, g = z & 3;
    int tx = threadIdx.x, ty = threadIdx.y;
#pragma unroll
    for (int r = 0; r < 32; r += 8)
        t[ty + r][tx] = g_qkv[(size_t)(b * SEQ + k0 + ty + r) * QKV_N +
                              D_MODEL + KV_DIM + g * 128 + n0 + tx];
    __syncthreads();
#pragma unroll
    for (int r = 0; r < 32; r += 8)
        g_Vt[((size_t)z * HEAD_DIM + n0 + ty + r) * SEQ + k0 + tx] =
            __float2half(t[tx][ty + r]);
}

// ---------------------------------------------------------------------------
// FA-2-style tensor-core attention (TQ=128). Softmax in log2 domain with
// fp32 ex2.approx; guards removed via rowm init -1e4 (masked -1e30 entries
// underflow to exactly 0 in fp32 ex2).
// ---------------------------------------------------------------------------
#define BS_Q   0
#define BS_K   34816
#define BS_V   69632
#define BS_KD  106496
#define ATT_SMEM 107008
#define SCALE_L2E 0.12753102f    // (1/sqrt(128)) * log2(e)

__global__ void __launch_bounds__(256, 1) attn_mma(const int* __restrict__ doc_ids)
{
    extern __shared__ char smem[];
    const uint32_t sb = smem_u32(smem);
    const uint32_t uQ = sb + BS_Q;

    const int qt = (int)(gridDim.x - 1) - (int)blockIdx.x;
    const int h = blockIdx.y, b = blockIdx.z;
    const int g = h >> 2;
    const int tid = threadIdx.x, w = tid >> 5, l = tid & 31;
    const int wm = w * 16;
    const int t0 = qt * 128;

    const __half* qsrc = g_Qh + (((size_t)(b * 16 + h)) * SEQ + t0) * HEAD_DIM;
#pragma unroll
    for (int j = 0; j < 8; j++) {
        int idx = tid + j * 256;
        int r = idx >> 4, c = idx & 15;
        CP_ASYNC16(uQ + (uint32_t)(r * 136 + c * 8) * 2, qsrc + r * 128 + c * 8);
    }
    CP_COMMIT();

    const int r0 = wm + (l >> 2);
    const int qi0 = t0 + r0, qi8 = qi0 + 8;
    const int dbase = b * SEQ;
    const int qd0 = doc_ids[dbase + qi0];
    const int qd8 = doc_ids[dbase + qi8];
    const int dq_min = doc_ids[dbase + t0];

    float rowm0 = -1e4f, rowm8 = -1e4f, rowl0 = 0.f, rowl8 = 0.f;
    float acc[16][4];
#pragma unroll
    for (int nf = 0; nf < 16; nf++)
#pragma unroll
        for (int q = 0; q < 4; q++) acc[nf][q] = 0.f;

    const __half* kbase = g_Kh + ((size_t)(b * 4 + g)) * SEQ * HEAD_DIM;
    const __half* vbase = g_Vt + ((size_t)(b * 4 + g) * HEAD_DIM) * SEQ;

    auto load_tile = [&](int t, int buf) {
        const __half* ks = kbase + (size_t)t * 64 * HEAD_DIM;
        const __half* vs = vbase + t * 64;
        uint32_t uk = sb + BS_K + buf * 17408;
        uint32_t uv = sb + BS_V + buf * 18432;
#pragma unroll
        for (int j = 0; j < 4; j++) {
            int idx = tid + j * 256;
            int r = idx >> 4, c = idx & 15;
            CP_ASYNC16(uk + (uint32_t)(r * 136 + c * 8) * 2, ks + r * 128 + c * 8);
        }
#pragma unroll
        for (int j = 0; j < 4; j++) {
            int idx = tid + j * 256;
            int r = idx >> 3, c = idx & 7;
            CP_ASYNC16(uv + (uint32_t)(r * 72 + c * 8) * 2, vs + (size_t)r * SEQ + c * 8);
        }
        if (tid < 64)
            ((int*)(smem + BS_KD + buf * 256))[tid] = doc_ids[dbase + t * 64 + tid];
    };

    const int ktmax = 2 * qt + 1;
    int kt = 0;
    while (kt <= ktmax && doc_ids[dbase + kt * 64 + 63] < dq_min) kt++;

    int p = 0;
    load_tile(kt, 0);
    CP_COMMIT();
    CP_WAIT0();
    __syncthreads();

    uint32_t qfr[4][2][4];
#pragma unroll
    for (int kb = 0; kb < 4; kb++)
#pragma unroll
        for (int s = 0; s < 2; s++)
            ldsm_x4(qfr[kb][s], uQ + (uint32_t)((wm + ((l >> 3) & 1) * 8 + (l & 7)) * 136 +
                    (kb * 4 + 2 * s + (l >> 4)) * 8) * 2);

    while (true) {
        int ktn = kt + 1;
        while (ktn <= ktmax && doc_ids[dbase + ktn * 64 + 63] < dq_min) ktn++;
        const bool havenext = (ktn <= ktmax);
        if (havenext) { load_tile(ktn, p ^ 1); CP_COMMIT(); }

        const uint32_t uk = sb + BS_K + p * 17408;
        const uint32_t uv = sb + BS_V + p * 18432;
        const int* kd = (const int*)(smem + BS_KD + p * 256);

        float e[8][4];
#pragma unroll
        for (int nf = 0; nf < 8; nf++)
#pragma unroll
            for (int q = 0; q < 4; q++) e[nf][q] = 0.f;

#pragma unroll
        for (int kb = 0; kb < 4; kb++) {
#pragma unroll
            for (int nf = 0; nf < 8; nf++) {
                uint32_t bfr[4];
                ldsm_x4(bfr, uk + (uint32_t)((nf * 8 + (l & 7)) * 136 +
                        (kb * 4 + (l >> 3)) * 8) * 2);
                mma16816(e[nf], qfr[kb][0], bfr[0], bfr[1]);
                mma16816(e[nf], qfr[kb][1], bfr[2], bfr[3]);
            }
        }

        // mask + scale into log2 domain
        const int kcol0 = kt * 64;
#pragma unroll
        for (int nf = 0; nf < 8; nf++) {
            int c = nf * 8 + (l & 3) * 2;
            int kj = kcol0 + c;
            int kdc = kd[c], kdc1 = kd[c + 1];
            e[nf][0] = (kj     > qi0 || qd0 != kdc ) ? -1e30f : e[nf][0] * SCALE_L2E;
            e[nf][1] = (kj + 1 > qi0 || qd0 != kdc1) ? -1e30f : e[nf][1] * SCALE_L2E;
            e[nf][2] = (kj     > qi8 || qd8 != kdc ) ? -1e30f : e[nf][2] * SCALE_L2E;
            e[nf][3] = (kj + 1 > qi8 || qd8 != kdc1) ? -1e30f : e[nf][3] * SCALE_L2E;
        }

        // row max (log2 domain); rowm >= -1e4 always
        float mx0 = rowm0, mx8 = rowm8;
#pragma unroll
        for (int nf = 0; nf < 8; nf++) {
            mx0 = fmaxf(mx0, fmaxf(e[nf][0], e[nf][1]));
            mx8 = fmaxf(mx8, fmaxf(e[nf][2], e[nf][3]));
        }
        mx0 = fmaxf(mx0, __shfl_xor_sync(0xffffffffu, mx0, 1));
        mx0 = fmaxf(mx0, __shfl_xor_sync(0xffffffffu, mx0, 2));
        mx8 = fmaxf(mx8, __shfl_xor_sync(0xffffffffu, mx8, 1));
        mx8 = fmaxf(mx8, __shfl_xor_sync(0xffffffffu, mx8, 2));

        float cf0 = ex2f(rowm0 - mx0);
        float cf8 = ex2f(rowm8 - mx8);

        // P = ex2(sv - mx) in fp32 (masked entries underflow to 0), pack fp16
        uint32_t pa[4][4];
        float ts0 = 0.f, ts8 = 0.f;
#pragma unroll
        for (int j = 0; j < 4; j++) {
            float p00 = ex2f(e[2 * j][0] - mx0);
            float p01 = ex2f(e[2 * j][1] - mx0);
            float p08 = ex2f(e[2 * j][2] - mx8);
            float p09 = ex2f(e[2 * j][3] - mx8);
            float p10 = ex2f(e[2 * j + 1][0] - mx0);
            float p11 = ex2f(e[2 * j + 1][1] - mx0);
            float p18 = ex2f(e[2 * j + 1][2] - mx8);
            float p19 = ex2f(e[2 * j + 1][3] - mx8);
            pa[j][0] = packh2(p00, p01);
            pa[j][1] = packh2(p08, p09);
            pa[j][2] = packh2(p10, p11);
            pa[j][3] = packh2(p18, p19);
            ts0 += (p00 + p01) + (p10 + p11);
            ts8 += (p08 + p09) + (p18 + p19);
        }
        ts0 += __shfl_xor_sync(0xffffffffu, ts0, 1);
        ts0 += __shfl_xor_sync(0xffffffffu, ts0, 2);
        ts8 += __shfl_xor_sync(0xffffffffu, ts8, 1);
        ts8 += __shfl_xor_sync(0xffffffffu, ts8, 2);
        rowm0 = mx0; rowm8 = mx8;
        rowl0 = rowl0 * cf0 + ts0;
        rowl8 = rowl8 * cf8 + ts8;

#pragma unroll
        for (int nf = 0; nf < 16; nf++) {
            acc[nf][0] *= cf0; acc[nf][1] *= cf0;
            acc[nf][2] *= cf8; acc[nf][3] *= cf8;
        }

#pragma unroll
        for (int kb2 = 0; kb2 < 2; kb2++) {
#pragma unroll
            for (int nf = 0; nf < 16; nf++) {
                uint32_t bfr[4];
                ldsm_x4(bfr, uv + (uint32_t)((nf * 8 + (l & 7)) * 72 +
                        (kb2 * 4 + (l >> 3)) * 8) * 2);
                mma16816(acc[nf], pa[2 * kb2],     bfr[0], bfr[1]);
                mma16816(acc[nf], pa[2 * kb2 + 1], bfr[2], bfr[3]);
            }
        }

        if (!havenext) break;
        CP_WAIT0();
        __syncthreads();
        p ^= 1;
        kt = ktn;
    }

    {
        float inv0 = 1.f / rowl0, inv8 = 1.f / rowl8;
        size_t row0 = (size_t)(dbase + qi0) * D_MODEL;
        size_t row8 = (size_t)(dbase + qi8) * D_MODEL;
#pragma unroll
        for (int nf = 0; nf < 16; nf++) {
            int c = h * 128 + nf * 8 + (l & 3) * 2;
            *(__half2*)(g_Aatt + row0 + c) =
                __floats2half2_rn(acc[nf][0] * inv0, acc[nf][1] * inv0);
            *(__half2*)(g_Aatt + row8 + c) =
                __floats2half2_rn(acc[nf][2] * inv8, acc[nf][3] * inv8);
        }
    }
}

// ---------------------------------------------------------------------------
extern "C" void kernel_launch(void* const* d_in, const int* in_sizes, int n_in,
                              void* d_out, int out_size)
{
    const float* x    = (const float*)d_in[0];
    const float* sinp = (const float*)d_in[1];
    const float* cosp = (const float*)d_in[2];
    const int*   doc  = (const int*)d_in[3];
    const float* Wqkv = (const float*)d_in[4];
    const float* Wo   = (const float*)d_in[5];
    float* out = (float*)d_out;

    float* qkv_ptr;
    __half *ax, *aatt, *bqkv, *bo;
    cudaGetSymbolAddress((void**)&qkv_ptr, g_qkv);
    cudaGetSymbolAddress((void**)&ax,   g_Ax);
    cudaGetSymbolAddress((void**)&aatt, g_Aatt);
    cudaGetSymbolAddress((void**)&bqkv, g_Bqkv);
    cudaGetSymbolAddress((void**)&bo,   g_Bo);

    cudaFuncSetAttribute(gemm_mma, cudaFuncAttributeMaxDynamicSharedMemorySize,
                         GSM_BYTES);
    cudaFuncSetAttribute(attn_mma, cudaFuncAttributeMaxDynamicSharedMemorySize,
                         ATT_SMEM);

    // 1) fp16 conversions
    conv_half4<<<(M_TOT * D_MODEL / 4) / 256, 256>>>(x, ax);
    convT_half<<<dim3(QKV_N / 32, D_MODEL / 32), dim3(32, 8)>>>(Wqkv, bqkv, QKV_N);

    // 2) QKV projection (R11 config: 128x128, 2 CTA/SM)
    gemm_mma<<<dim3(QKV_N / 128, M_TOT / 128), 256, GSM_BYTES>>>(ax, bqkv, qkv_ptr,
                                                                 QKV_N, D_MODEL);

    // 3) RoPE + head-major fp16 Q/K; V transpose
    rope_conv<<<(M_TOT * 20 * 64) / 256, 256>>>(sinp, cosp);
    vt_conv<<<dim3(HEAD_DIM / 32, SEQ / 32, BATCHN * 4), dim3(32, 8)>>>();

    // 4) FA-2-style tensor-core attention (fp32 ex2 softmax, guard-free)
    attn_mma<<<dim3(SEQ / 128, NUM_HEADS, BATCHN), 256, ATT_SMEM>>>(doc);

    // 5) Output projection
    convT_half<<<dim3(D_MODEL / 32, D_MODEL / 32), dim3(32, 8)>>>(Wo, bo, D_MODEL);
    gemm_mma<<<dim3(D_MODEL / 128, M_TOT / 128), 256, GSM_BYTES>>>(aatt, bo, out,
                                                                   D_MODEL, D_MODEL);
}

// round 16
// speedup vs baseline: 1.0800x; 1.0054x over previous
#include <cuda_runtime.h>
#include <cuda_fp16.h>
#include <cstdint>
#include <math.h>

#define D_MODEL   2048
#define NUM_HEADS 16
#define HEAD_DIM  128
#define KV_DIM    512
#define QKV_N     3072
#define BATCHN    2
#define SEQ       2048
#define M_TOT     4096

// ---------------------------------------------------------------------------
// Scratch (__device__ globals; allocation-free rule)
// ---------------------------------------------------------------------------
__device__ __align__(16) __half g_qkvh[(size_t)M_TOT * QKV_N];   // fp16 QKV
__device__ __align__(16) __half g_Ax[(size_t)M_TOT * D_MODEL];
__device__ __align__(16) __half g_Aatt[(size_t)M_TOT * D_MODEL];
__device__ __align__(16) __half g_Bqkv[(size_t)QKV_N * D_MODEL];
__device__ __align__(16) __half g_Bo[(size_t)D_MODEL * D_MODEL];
__device__ __align__(16) __half g_Qh[(size_t)BATCHN * NUM_HEADS * SEQ * HEAD_DIM];
__device__ __align__(16) __half g_Kh[(size_t)BATCHN * 4 * SEQ * HEAD_DIM];
__device__ __align__(16) __half g_Vt[(size_t)BATCHN * 4 * HEAD_DIM * SEQ];

__device__ __forceinline__ uint32_t smem_u32(const void* p) {
    uint32_t a;
    asm("{ .reg .u64 t; cvta.to.shared.u64 t, %1; cvt.u32.u64 %0, t; }" : "=r"(a) : "l"(p));
    return a;
}
__device__ __forceinline__ void ldsm_x4(uint32_t* r, uint32_t addr) {
    asm volatile("ldmatrix.sync.aligned.m8n8.x4.shared.b16 {%0,%1,%2,%3}, [%4];"
                 : "=r"(r[0]), "=r"(r[1]), "=r"(r[2]), "=r"(r[3]) : "r"(addr) : "memory");
}
__device__ __forceinline__ void mma16816(float* c, const uint32_t* a,
                                         uint32_t b0, uint32_t b1) {
    asm volatile("mma.sync.aligned.m16n8k16.row.col.f32.f16.f16.f32 "
                 "{%0,%1,%2,%3},{%4,%5,%6,%7},{%8,%9},{%0,%1,%2,%3};"
                 : "+f"(c[0]), "+f"(c[1]), "+f"(c[2]), "+f"(c[3])
                 : "r"(a[0]), "r"(a[1]), "r"(a[2]), "r"(a[3]), "r"(b0), "r"(b1));
}
__device__ __forceinline__ uint32_t packh2(float a, float b) {
    __half2 h = __floats2half2_rn(a, b);
    return *(uint32_t*)&h;
}
__device__ __forceinline__ float ex2f(float x) {
    float y; asm("ex2.approx.f32 %0, %1;" : "=f"(y) : "f"(x)); return y;
}
#define CP_ASYNC16(dst, src) \
    asm volatile("cp.async.cg.shared.global [%0], [%1], 16;\n" :: "r"(dst), "l"(src))
#define CP_COMMIT() asm volatile("cp.async.commit_group;\n" ::: "memory")
#define CP_WAIT0()  asm volatile("cp.async.wait_group 0;\n" ::: "memory")
#define CP_WAIT1()  asm volatile("cp.async.wait_group 1;\n" ::: "memory")

#define GSM_BYTES (6 * 5120 * 2)   // 3-stage pipeline: 3 A-bufs + 3 B-bufs

// ---------------------------------------------------------------------------
// fp16 tensor-core GEMM, 128x128 tile, 3-stage cp.async. fp32 output.
// ---------------------------------------------------------------------------
__global__ void __launch_bounds__(256, 2) gemm_mma(const __half* __restrict__ A,
                                                   const __half* __restrict__ B,
                                                   float* __restrict__ C,
                                                   int N, int K)
{
    extern __shared__ __half gsm[];
    __half* As = gsm;
    __half* Bs = gsm + 3 * 5120;
    const int tid = threadIdx.x;
    const int w = tid >> 5, l = tid & 31;
    const int brow = blockIdx.y * 128, bcol = blockIdx.x * 128;
    const int wm = (w >> 2) * 64, wn = (w & 3) * 32;
    const uint32_t sa0 = smem_u32(As), sb0 = smem_u32(Bs);
    const int NIT = K >> 5;

    float acc[4][4][4];
#pragma unroll
    for (int a = 0; a < 4; a++)
#pragma unroll
        for (int b2 = 0; b2 < 4; b2++)
#pragma unroll
            for (int c = 0; c < 4; c++) acc[a][b2][c] = 0.f;

    const int lr0 = tid >> 2, lkc = tid & 3;
    const __half* Ag = A + (size_t)brow * K;
    const __half* Bg = B + (size_t)bcol * K;

    auto LOAD = [&](int buf, int k0) {
#pragma unroll
        for (int j = 0; j < 2; j++) {
            int r = lr0 + j * 64;
            uint32_t so = (uint32_t)(buf * 5120 + r * 40 + lkc * 8) * 2;
            CP_ASYNC16(sa0 + so, Ag + (size_t)r * K + k0 + lkc * 8);
            CP_ASYNC16(sb0 + so, Bg + (size_t)r * K + k0 + lkc * 8);
        }
        CP_COMMIT();
    };

    LOAD(0, 0);
    LOAD(1, 32);

    for (int i = 0; i < NIT; i++) {
        const int p = i % 3;
        if (i == NIT - 1) { CP_WAIT0(); } else { CP_WAIT1(); }
        __syncthreads();
        if (i + 2 < NIT) LOAD((i + 2) % 3, (i + 2) * 32);

        uint32_t bfr[4][4];
#pragma unroll
        for (int nf = 0; nf < 4; nf++)
            ldsm_x4(bfr[nf], sb0 + (uint32_t)(p * 5120 +
                    (wn + nf * 8 + (l & 7)) * 40 + (l >> 3) * 8) * 2);

#pragma unroll
        for (int s = 0; s < 2; s++) {
            uint32_t afr[4][4];
#pragma unroll
            for (int mf = 0; mf < 4; mf++) {
                int row = wm + mf * 16 + ((l >> 3) & 1) * 8 + (l & 7);
                int chunk = 2 * s + (l >> 4);
                ldsm_x4(afr[mf], sa0 + (uint32_t)(p * 5120 + row * 40 + chunk * 8) * 2);
            }
#pragma unroll
            for (int mf = 0; mf < 4; mf++)
#pragma unroll
                for (int nf = 0; nf < 4; nf++)
                    mma16816(acc[mf][nf], afr[mf], bfr[nf][2 * s], bfr[nf][2 * s + 1]);
        }
    }

#pragma unroll
    for (int mf = 0; mf < 4; mf++) {
        int r0 = brow + wm + mf * 16 + (l >> 2);
#pragma unroll
        for (int nf = 0; nf < 4; nf++) {
            int c = bcol + wn + nf * 8 + (l & 3) * 2;
            *(float2*)(C + (size_t)r0 * N + c) = make_float2(acc[mf][nf][0], acc[mf][nf][1]);
            *(float2*)(C + (size_t)(r0 + 8) * N + c) = make_float2(acc[mf][nf][2], acc[mf][nf][3]);
        }
    }
}

// ---------------------------------------------------------------------------
// Same GEMM, fp16 output (for the QKV intermediate).
// ---------------------------------------------------------------------------
__global__ void __launch_bounds__(256, 2) gemm_mma_h(const __half* __restrict__ A,
                                                     const __half* __restrict__ B,
                                                     __half* __restrict__ C,
                                                     int N, int K)
{
    extern __shared__ __half gsm[];
    __half* As = gsm;
    __half* Bs = gsm + 3 * 5120;
    const int tid = threadIdx.x;
    const int w = tid >> 5, l = tid & 31;
    const int brow = blockIdx.y * 128, bcol = blockIdx.x * 128;
    const int wm = (w >> 2) * 64, wn = (w & 3) * 32;
    const uint32_t sa0 = smem_u32(As), sb0 = smem_u32(Bs);
    const int NIT = K >> 5;

    float acc[4][4][4];
#pragma unroll
    for (int a = 0; a < 4; a++)
#pragma unroll
        for (int b2 = 0; b2 < 4; b2++)
#pragma unroll
            for (int c = 0; c < 4; c++) acc[a][b2][c] = 0.f;

    const int lr0 = tid >> 2, lkc = tid & 3;
    const __half* Ag = A + (size_t)brow * K;
    const __half* Bg = B + (size_t)bcol * K;

    auto LOAD = [&](int buf, int k0) {
#pragma unroll
        for (int j = 0; j < 2; j++) {
            int r = lr0 + j * 64;
            uint32_t so = (uint32_t)(buf * 5120 + r * 40 + lkc * 8) * 2;
            CP_ASYNC16(sa0 + so, Ag + (size_t)r * K + k0 + lkc * 8);
            CP_ASYNC16(sb0 + so, Bg + (size_t)r * K + k0 + lkc * 8);
        }
        CP_COMMIT();
    };

    LOAD(0, 0);
    LOAD(1, 32);

    for (int i = 0; i < NIT; i++) {
        const int p = i % 3;
        if (i == NIT - 1) { CP_WAIT0(); } else { CP_WAIT1(); }
        __syncthreads();
        if (i + 2 < NIT) LOAD((i + 2) % 3, (i + 2) * 32);

        uint32_t bfr[4][4];
#pragma unroll
        for (int nf = 0; nf < 4; nf++)
            ldsm_x4(bfr[nf], sb0 + (uint32_t)(p * 5120 +
                    (wn + nf * 8 + (l & 7)) * 40 + (l >> 3) * 8) * 2);

#pragma unroll
        for (int s = 0; s < 2; s++) {
            uint32_t afr[4][4];
#pragma unroll
            for (int mf = 0; mf < 4; mf++) {
                int row = wm + mf * 16 + ((l >> 3) & 1) * 8 + (l & 7);
                int chunk = 2 * s + (l >> 4);
                ldsm_x4(afr[mf], sa0 + (uint32_t)(p * 5120 + row * 40 + chunk * 8) * 2);
            }
#pragma unroll
            for (int mf = 0; mf < 4; mf++)
#pragma unroll
                for (int nf = 0; nf < 4; nf++)
                    mma16816(acc[mf][nf], afr[mf], bfr[nf][2 * s], bfr[nf][2 * s + 1]);
        }
    }

#pragma unroll
    for (int mf = 0; mf < 4; mf++) {
        int r0 = brow + wm + mf * 16 + (l >> 2);
#pragma unroll
        for (int nf = 0; nf < 4; nf++) {
            int c = bcol + wn + nf * 8 + (l & 3) * 2;
            *(__half2*)(C + (size_t)r0 * N + c) =
                __floats2half2_rn(acc[mf][nf][0], acc[mf][nf][1]);
            *(__half2*)(C + (size_t)(r0 + 8) * N + c) =
                __floats2half2_rn(acc[mf][nf][2], acc[mf][nf][3]);
        }
    }
}

// ---------------------------------------------------------------------------
// Converts
// ---------------------------------------------------------------------------
__global__ void conv_half4(const float* __restrict__ s, __half* __restrict__ d)
{
    int i = blockIdx.x * blockDim.x + threadIdx.x;
    float4 v = ((const float4*)s)[i];
    ((__half2*)d)[2 * i]     = __floats2half2_rn(v.x, v.y);
    ((__half2*)d)[2 * i + 1] = __floats2half2_rn(v.z, v.w);
}

__global__ void convT_half(const float* __restrict__ W,
                           __half* __restrict__ dst, int Ncols)
{
    __shared__ float t[32][33];
    int k0 = blockIdx.y * 32, n0 = blockIdx.x * 32;
    int tx = threadIdx.x, ty = threadIdx.y;
#pragma unroll
    for (int r = 0; r < 32; r += 8)
        t[ty + r][tx] = W[(size_t)(k0 + ty + r) * Ncols + n0 + tx];
    __syncthreads();
#pragma unroll
    for (int r = 0; r < 32; r += 8)
        dst[(size_t)(n0 + ty + r) * D_MODEL + k0 + tx] = __float2half(t[tx][ty + r]);
}

// RoPE reads fp16 g_qkvh, math in fp32, writes fp16 head-major Qh/Kh
__global__ void rope_conv(const float* __restrict__ sinp,
                          const float* __restrict__ cosp)
{
    int i = blockIdx.x * blockDim.x + threadIdx.x;
    int d  = i & 63;
    int hh = (i >> 6) % 20;
    int m  = i / (64 * 20);
    int t  = m & (SEQ - 1);
    int b  = m >> 11;
    int col = (hh < 16) ? hh * 128 : D_MODEL + (hh - 16) * 128;
    float s = sinp[t * 64 + d];
    float c = cosp[t * 64 + d];
    const __half* p = g_qkvh + (size_t)m * QKV_N + col;
    float x1 = __half2float(p[d]), x2 = __half2float(p[d + 64]);
    float y1 = x1 * c - x2 * s;
    float y2 = x2 * c + x1 * s;
    __half* dst = (hh < 16)
        ? g_Qh + (((size_t)(b * 16 + hh)) * SEQ + t) * HEAD_DIM
        : g_Kh + (((size_t)(b * 4 + (hh - 16))) * SEQ + t) * HEAD_DIM;
    dst[d]      = __float2half(y1);
    dst[d + 64] = __float2half(y2);
}

// V transpose: fp16 g_qkvh V cols -> g_Vt[b*4+g][d][s]
__global__ void vt_conv()
{
    __shared__ __half t[32][34];
    int n0 = blockIdx.x * 32;
    int k0 = blockIdx.y * 32;
    int z  = blockIdx.z;
    int b = z >> 2, g = z & 3;
    int tx = threadIdx.x, ty = threadIdx.y;
#pragma unroll
    for (int r = 0; r < 32; r += 8)
        t[ty + r][tx] = g_qkvh[(size_t)(b * SEQ + k0 + ty + r) * QKV_N +
                               D_MODEL + KV_DIM + g * 128 + n0 + tx];
    __syncthreads();
#pragma unroll
    for (int r = 0; r < 32; r += 8)
        g_Vt[((size_t)z * HEAD_DIM + n0 + ty + r) * SEQ + k0 + tx] = t[tx][ty + r];
}

// ---------------------------------------------------------------------------
// FA-2-style tensor-core attention (TQ=128), fp32 ex2 log2-domain softmax
// (byte-identical to R15 passing kernel).
// ---------------------------------------------------------------------------
#define BS_Q   0
#define BS_K   34816
#define BS_V   69632
#define BS_KD  106496
#define ATT_SMEM 107008
#define SCALE_L2E 0.12753102f    // (1/sqrt(128)) * log2(e)

__global__ void __launch_bounds__(256, 1) attn_mma(const int* __restrict__ doc_ids)
{
    extern __shared__ char smem[];
    const uint32_t sb = smem_u32(smem);
    const uint32_t uQ = sb + BS_Q;

    const int qt = (int)(gridDim.x - 1) - (int)blockIdx.x;
    const int h = blockIdx.y, b = blockIdx.z;
    const int g = h >> 2;
    const int tid = threadIdx.x, w = tid >> 5, l = tid & 31;
    const int wm = w * 16;
    const int t0 = qt * 128;

    const __half* qsrc = g_Qh + (((size_t)(b * 16 + h)) * SEQ + t0) * HEAD_DIM;
#pragma unroll
    for (int j = 0; j < 8; j++) {
        int idx = tid + j * 256;
        int r = idx >> 4, c = idx & 15;
        CP_ASYNC16(uQ + (uint32_t)(r * 136 + c * 8) * 2, qsrc + r * 128 + c * 8);
    }
    CP_COMMIT();

    const int r0 = wm + (l >> 2);
    const int qi0 = t0 + r0, qi8 = qi0 + 8;
    const int dbase = b * SEQ;
    const int qd0 = doc_ids[dbase + qi0];
    const int qd8 = doc_ids[dbase + qi8];
    const int dq_min = doc_ids[dbase + t0];

    float rowm0 = -1e4f, rowm8 = -1e4f, rowl0 = 0.f, rowl8 = 0.f;
    float acc[16][4];
#pragma unroll
    for (int nf = 0; nf < 16; nf++)
#pragma unroll
        for (int q = 0; q < 4; q++) acc[nf][q] = 0.f;

    const __half* kbase = g_Kh + ((size_t)(b * 4 + g)) * SEQ * HEAD_DIM;
    const __half* vbase = g_Vt + ((size_t)(b * 4 + g) * HEAD_DIM) * SEQ;

    auto load_tile = [&](int t, int buf) {
        const __half* ks = kbase + (size_t)t * 64 * HEAD_DIM;
        const __half* vs = vbase + t * 64;
        uint32_t uk = sb + BS_K + buf * 17408;
        uint32_t uv = sb + BS_V + buf * 18432;
#pragma unroll
        for (int j = 0; j < 4; j++) {
            int idx = tid + j * 256;
            int r = idx >> 4, c = idx & 15;
            CP_ASYNC16(uk + (uint32_t)(r * 136 + c * 8) * 2, ks + r * 128 + c * 8);
        }
#pragma unroll
        for (int j = 0; j < 4; j++) {
            int idx = tid + j * 256;
            int r = idx >> 3, c = idx & 7;
            CP_ASYNC16(uv + (uint32_t)(r * 72 + c * 8) * 2, vs + (size_t)r * SEQ + c * 8);
        }
        if (tid < 64)
            ((int*)(smem + BS_KD + buf * 256))[tid] = doc_ids[dbase + t * 64 + tid];
    };

    const int ktmax = 2 * qt + 1;
    int kt = 0;
    while (kt <= ktmax && doc_ids[dbase + kt * 64 + 63] < dq_min) kt++;

    int p = 0;
    load_tile(kt, 0);
    CP_COMMIT();
    CP_WAIT0();
    __syncthreads();

    uint32_t qfr[4][2][4];
#pragma unroll
    for (int kb = 0; kb < 4; kb++)
#pragma unroll
        for (int s = 0; s < 2; s++)
            ldsm_x4(qfr[kb][s], uQ + (uint32_t)((wm + ((l >> 3) & 1) * 8 + (l & 7)) * 136 +
                    (kb * 4 + 2 * s + (l >> 4)) * 8) * 2);

    while (true) {
        int ktn = kt + 1;
        while (ktn <= ktmax && doc_ids[dbase + ktn * 64 + 63] < dq_min) ktn++;
        const bool havenext = (ktn <= ktmax);
        if (havenext) { load_tile(ktn, p ^ 1); CP_COMMIT(); }

        const uint32_t uk = sb + BS_K + p * 17408;
        const uint32_t uv = sb + BS_V + p * 18432;
        const int* kd = (const int*)(smem + BS_KD + p * 256);

        float e[8][4];
#pragma unroll
        for (int nf = 0; nf < 8; nf++)
#pragma unroll
            for (int q = 0; q < 4; q++) e[nf][q] = 0.f;

#pragma unroll
        for (int kb = 0; kb < 4; kb++) {
#pragma unroll
            for (int nf = 0; nf < 8; nf++) {
                uint32_t bfr[4];
                ldsm_x4(bfr, uk + (uint32_t)((nf * 8 + (l & 7)) * 136 +
                        (kb * 4 + (l >> 3)) * 8) * 2);
                mma16816(e[nf], qfr[kb][0], bfr[0], bfr[1]);
                mma16816(e[nf], qfr[kb][1], bfr[2], bfr[3]);
            }
        }

        // mask + scale into log2 domain
        const int kcol0 = kt * 64;
#pragma unroll
        for (int nf = 0; nf < 8; nf++) {
            int c = nf * 8 + (l & 3) * 2;
            int kj = kcol0 + c;
            int kdc = kd[c], kdc1 = kd[c + 1];
            e[nf][0] = (kj     > qi0 || qd0 != kdc ) ? -1e30f : e[nf][0] * SCALE_L2E;
            e[nf][1] = (kj + 1 > qi0 || qd0 != kdc1) ? -1e30f : e[nf][1] * SCALE_L2E;
            e[nf][2] = (kj     > qi8 || qd8 != kdc ) ? -1e30f : e[nf][2] * SCALE_L2E;
            e[nf][3] = (kj + 1 > qi8 || qd8 != kdc1) ? -1e30f : e[nf][3] * SCALE_L2E;
        }

        // row max (log2 domain); rowm >= -1e4 always
        float mx0 = rowm0, mx8 = rowm8;
#pragma unroll
        for (int nf = 0; nf < 8; nf++) {
            mx0 = fmaxf(mx0, fmaxf(e[nf][0], e[nf][1]));
            mx8 = fmaxf(mx8, fmaxf(e[nf][2], e[nf][3]));
        }
        mx0 = fmaxf(mx0, __shfl_xor_sync(0xffffffffu, mx0, 1));
        mx0 = fmaxf(mx0, __shfl_xor_sync(0xffffffffu, mx0, 2));
        mx8 = fmaxf(mx8, __shfl_xor_sync(0xffffffffu, mx8, 1));
        mx8 = fmaxf(mx8, __shfl_xor_sync(0xffffffffu, mx8, 2));

        float cf0 = ex2f(rowm0 - mx0);
        float cf8 = ex2f(rowm8 - mx8);

        // P = ex2(sv - mx) in fp32 (masked entries underflow to 0), pack fp16
        uint32_t pa[4][4];
        float ts0 = 0.f, ts8 = 0.f;
#pragma unroll
        for (int j = 0; j < 4; j++) {
            float p00 = ex2f(e[2 * j][0] - mx0);
            float p01 = ex2f(e[2 * j][1] - mx0);
            float p08 = ex2f(e[2 * j][2] - mx8);
            float p09 = ex2f(e[2 * j][3] - mx8);
            float p10 = ex2f(e[2 * j + 1][0] - mx0);
            float p11 = ex2f(e[2 * j + 1][1] - mx0);
            float p18 = ex2f(e[2 * j + 1][2] - mx8);
            float p19 = ex2f(e[2 * j + 1][3] - mx8);
            pa[j][0] = packh2(p00, p01);
            pa[j][1] = packh2(p08, p09);
            pa[j][2] = packh2(p10, p11);
            pa[j][3] = packh2(p18, p19);
            ts0 += (p00 + p01) + (p10 + p11);
            ts8 += (p08 + p09) + (p18 + p19);
        }
        ts0 += __shfl_xor_sync(0xffffffffu, ts0, 1);
        ts0 += __shfl_xor_sync(0xffffffffu, ts0, 2);
        ts8 += __shfl_xor_sync(0xffffffffu, ts8, 1);
        ts8 += __shfl_xor_sync(0xffffffffu, ts8, 2);
        rowm0 = mx0; rowm8 = mx8;
        rowl0 = rowl0 * cf0 + ts0;
        rowl8 = rowl8 * cf8 + ts8;

#pragma unroll
        for (int nf = 0; nf < 16; nf++) {
            acc[nf][0] *= cf0; acc[nf][1] *= cf0;
            acc[nf][2] *= cf8; acc[nf][3] *= cf8;
        }

#pragma unroll
        for (int kb2 = 0; kb2 < 2; kb2++) {
#pragma unroll
            for (int nf = 0; nf < 16; nf++) {
                uint32_t bfr[4];
                ldsm_x4(bfr, uv + (uint32_t)((nf * 8 + (l & 7)) * 72 +
                        (kb2 * 4 + (l >> 3)) * 8) * 2);
                mma16816(acc[nf], pa[2 * kb2],     bfr[0], bfr[1]);
                mma16816(acc[nf], pa[2 * kb2 + 1], bfr[2], bfr[3]);
            }
        }

        if (!havenext) break;
        CP_WAIT0();
        __syncthreads();
        p ^= 1;
        kt = ktn;
    }

    {
        float inv0 = 1.f / rowl0, inv8 = 1.f / rowl8;
        size_t row0 = (size_t)(dbase + qi0) * D_MODEL;
        size_t row8 = (size_t)(dbase + qi8) * D_MODEL;
#pragma unroll
        for (int nf = 0; nf < 16; nf++) {
            int c = h * 128 + nf * 8 + (l & 3) * 2;
            *(__half2*)(g_Aatt + row0 + c) =
                __floats2half2_rn(acc[nf][0] * inv0, acc[nf][1] * inv0);
            *(__half2*)(g_Aatt + row8 + c) =
                __floats2half2_rn(acc[nf][2] * inv8, acc[nf][3] * inv8);
        }
    }
}

// ---------------------------------------------------------------------------
extern "C" void kernel_launch(void* const* d_in, const int* in_sizes, int n_in,
                              void* d_out, int out_size)
{
    const float* x    = (const float*)d_in[0];
    const float* sinp = (const float*)d_in[1];
    const float* cosp = (const float*)d_in[2];
    const int*   doc  = (const int*)d_in[3];
    const float* Wqkv = (const float*)d_in[4];
    const float* Wo   = (const float*)d_in[5];
    float* out = (float*)d_out;

    __half *qkvh, *ax, *aatt, *bqkv, *bo;
    cudaGetSymbolAddress((void**)&qkvh, g_qkvh);
    cudaGetSymbolAddress((void**)&ax,   g_Ax);
    cudaGetSymbolAddress((void**)&aatt, g_Aatt);
    cudaGetSymbolAddress((void**)&bqkv, g_Bqkv);
    cudaGetSymbolAddress((void**)&bo,   g_Bo);

    cudaFuncSetAttribute(gemm_mma, cudaFuncAttributeMaxDynamicSharedMemorySize,
                         GSM_BYTES);
    cudaFuncSetAttribute(gemm_mma_h, cudaFuncAttributeMaxDynamicSharedMemorySize,
                         GSM_BYTES);
    cudaFuncSetAttribute(attn_mma, cudaFuncAttributeMaxDynamicSharedMemorySize,
                         ATT_SMEM);

    // 1) fp16 conversions
    conv_half4<<<(M_TOT * D_MODEL / 4) / 256, 256>>>(x, ax);
    convT_half<<<dim3(QKV_N / 32, D_MODEL / 32), dim3(32, 8)>>>(Wqkv, bqkv, QKV_N);

    // 2) QKV projection -> fp16 intermediate (halved traffic)
    gemm_mma_h<<<dim3(QKV_N / 128, M_TOT / 128), 256, GSM_BYTES>>>(ax, bqkv, qkvh,
                                                                   QKV_N, D_MODEL);

    // 3) RoPE + head-major fp16 Q/K; V transpose (fp16 reads)
    rope_conv<<<(M_TOT * 20 * 64) / 256, 256>>>(sinp, cosp);
    vt_conv<<<dim3(HEAD_DIM / 32, SEQ / 32, BATCHN * 4), dim3(32, 8)>>>();

    // 4) FA-2-style tensor-core attention
    attn_mma<<<dim3(SEQ / 128, NUM_HEADS, BATCHN), 256, ATT_SMEM>>>(doc);

    // 5) Output projection (fp32 out)
    convT_half<<<dim3(D_MODEL / 32, D_MODEL / 32), dim3(32, 8)>>>(Wo, bo, D_MODEL);
    gemm_mma<<<dim3(D_MODEL / 128, M_TOT / 128), 256, GSM_BYTES>>>(aatt, bo, out,
                                                                   D_MODEL, D_MODEL);
}